// round 2
// baseline (speedup 1.0000x reference)
#include <cuda_runtime.h>
#include <cuda_bf16.h>
#include <math.h>

// Problem dims
#define BB 64
#define TT 1024
#define II 128
#define HH 256
#define YSZ (BB*TT*HH)   // 16777216

// ---------------- scratch (device globals; no allocs allowed) ----------------
__device__ float g_G[BB * TT * 512];    // gate pre-activations (x-part + bias), reused by both layers
__device__ float g_y1[BB * TT * HH];    // layer-1 outputs

// ---------------- f32x2 helpers ----------------
__device__ __forceinline__ unsigned long long pack2(float lo, float hi) {
    unsigned long long r;
    asm("mov.b64 %0, {%1, %2};" : "=l"(r) : "f"(lo), "f"(hi));
    return r;
}
__device__ __forceinline__ void unpack2(unsigned long long v, float& lo, float& hi) {
    asm("mov.b64 {%0, %1}, %2;" : "=f"(lo), "=f"(hi) : "l"(v));
}
__device__ __forceinline__ unsigned long long fma2(unsigned long long a, unsigned long long b,
                                                   unsigned long long c) {
    unsigned long long d;
    asm("fma.rn.f32x2 %0, %1, %2, %3;" : "=l"(d) : "l"(a), "l"(b), "l"(c));
    return d;
}

// ---------------- GEMM: G[m, 0:512] = A[m,:K] @ {Wf|Wc}[:K, :] + bias ----------------
// Grid: (4 n-tiles of 128, M/128). nt 0,1 -> f gate cols 0..255 ; nt 2,3 -> c gate cols 256..511
#define GM_BM 128
#define GM_BN 128
#define GM_BK 8

__global__ void __launch_bounds__(256) gemm_gates(
    const float* __restrict__ A, int lda, int K,
    const float* __restrict__ Wf, const float* __restrict__ Wc,
    const float* __restrict__ bf, const float* __restrict__ bc,
    float* __restrict__ G)
{
    __shared__ __align__(16) float As[GM_BK][GM_BM];
    __shared__ __align__(16) float Bs[GM_BK][GM_BN];

    int nt = blockIdx.x;                 // 0..3
    int m0 = blockIdx.y * GM_BM;
    const float* W  = (nt < 2) ? Wf : Wc;
    const float* bs = (nt < 2) ? bf : bc;
    int nbase = (nt & 1) * 128;

    int tid = threadIdx.x;
    int tx = tid & 15;        // n dir, 8 cols each
    int ty = tid >> 4;        // m dir, 8 rows each

    unsigned long long cc[8][4];
#pragma unroll
    for (int i = 0; i < 8; i++)
#pragma unroll
        for (int j = 0; j < 4; j++) cc[i][j] = 0ull;

    int arow = tid >> 1;            // 0..127
    int acol = (tid & 1) * 4;       // 0 or 4
    int brow = tid >> 5;            // 0..7
    int bcol = (tid & 31) * 4;      // 0..124

    for (int k0 = 0; k0 < K; k0 += GM_BK) {
        float4 av = *reinterpret_cast<const float4*>(&A[(size_t)(m0 + arow) * lda + k0 + acol]);
        As[acol + 0][arow] = av.x;
        As[acol + 1][arow] = av.y;
        As[acol + 2][arow] = av.z;
        As[acol + 3][arow] = av.w;
        float4 bv = *reinterpret_cast<const float4*>(&W[(size_t)(k0 + brow) * 256 + nbase + bcol]);
        *reinterpret_cast<float4*>(&Bs[brow][bcol]) = bv;
        __syncthreads();
#pragma unroll
        for (int kk = 0; kk < GM_BK; kk++) {
            float a[8];
            *reinterpret_cast<float4*>(a)     = *reinterpret_cast<const float4*>(&As[kk][ty * 8]);
            *reinterpret_cast<float4*>(a + 4) = *reinterpret_cast<const float4*>(&As[kk][ty * 8 + 4]);
            const ulonglong2* bu2 = reinterpret_cast<const ulonglong2*>(&Bs[kk][tx * 8]);
            ulonglong2 b01 = bu2[0];
            ulonglong2 b23 = bu2[1];
            unsigned long long bp[4] = {b01.x, b01.y, b23.x, b23.y};
#pragma unroll
            for (int i = 0; i < 8; i++) {
                unsigned long long ap = pack2(a[i], a[i]);
#pragma unroll
                for (int j = 0; j < 4; j++) cc[i][j] = fma2(ap, bp[j], cc[i][j]);
            }
        }
        __syncthreads();
    }
#pragma unroll
    for (int i = 0; i < 8; i++) {
        int m = m0 + ty * 8 + i;
        float* gr = &G[(size_t)m * 512 + nt * 128 + tx * 8];
#pragma unroll
        for (int j = 0; j < 4; j++) {
            float lo, hi;
            unpack2(cc[i][j], lo, hi);
            int cl = nbase + tx * 8 + 2 * j;
            float2 st;
            st.x = lo + bs[cl];
            st.y = hi + bs[cl + 1];
            *reinterpret_cast<float2*>(&gr[2 * j]) = st;
        }
    }
}

// ---------------- Recurrent sweep ----------------
// 64 batches, one 2-CTA cluster per batch. Each CTA owns 128 h-columns (both gates = 256 outputs).
// Weights: per thread 64 f32x2 pairs over its K-half of 128: REGP pairs in regs, SMEMP pairs in smem.
#define REC_THREADS 512
#define REGP 28
#define SMEMP 36
#define WSM_V2 ((SMEMP/2) * 2 * 256)           // ulonglong2 elements
#define WSM_BYTES (WSM_V2 * 16)                // 147456 bytes

__global__ void __launch_bounds__(REC_THREADS, 1) rec_kernel(
    const float* __restrict__ G, const float* __restrict__ Wf, const float* __restrict__ Wc,
    int xdim, float* __restrict__ Y, float* __restrict__ hidOut)
{
    extern __shared__ __align__(16) unsigned char smem_raw[];
    ulonglong2* wsmV2 = reinterpret_cast<ulonglong2*>(smem_raw);

    __shared__ __align__(16) float hsm[2 * 256];   // double-buffered full h
    __shared__ float fbuf[128];
    __shared__ float cbuf[128];

    int tid  = threadIdx.x;
    int b    = blockIdx.x >> 1;
    int rank = blockIdx.x & 1;
    int lane = tid & 31;
    int warp = tid >> 5;
    int kh   = (lane >> 4) & 1;               // which K-half this thread covers
    int u    = warp * 16 + (lane & 15);       // output index within CTA: 0..127 f, 128..255 c
    int colLocal = u & 127;
    int col  = rank * 128 + colLocal;         // global h column
    bool isF = (u < 128);
    const float* Wsrc = (isF ? Wf : Wc) + (size_t)xdim * 256;   // h-part rows of the weight
    int kb = kh * 128;

    // --- load weights: regs + smem ---
    unsigned long long wreg[REGP];
#pragma unroll
    for (int i = 0; i < REGP; i++) {
        int k = kb + 2 * i;
        wreg[i] = pack2(Wsrc[(size_t)k * 256 + col], Wsrc[(size_t)(k + 1) * 256 + col]);
    }
#pragma unroll
    for (int ii = 0; ii < SMEMP / 2; ii++) {
        int k = kb + 2 * (REGP + 2 * ii);
        ulonglong2 wv;
        wv.x = pack2(Wsrc[(size_t)k * 256 + col],       Wsrc[(size_t)(k + 1) * 256 + col]);
        wv.y = pack2(Wsrc[(size_t)(k + 2) * 256 + col], Wsrc[(size_t)(k + 3) * 256 + col]);
        wsmV2[(ii * 2 + kh) * 256 + u] = wv;
    }
    if (tid < 2 * 256) hsm[tid] = 0.0f;   // zero both h buffers
    __syncthreads();
    // cluster barrier: peer must not receive DSMEM h stores before init done
    asm volatile("barrier.cluster.arrive.aligned;" ::: "memory");
    asm volatile("barrier.cluster.wait.aligned;"   ::: "memory");

    const ulonglong2* hsmV2 = reinterpret_cast<const ulonglong2*>(hsm);  // 64 v2 per buffer
    int og = isF ? col : (256 + col);
    const float* Grow = G + (size_t)b * TT * 512 + og;
    float* Yrow = Y + (size_t)b * TT * HH;

    for (int t = 0; t < TT; t++) {
        int cur = t & 1;
        unsigned long long acc0 = 0ull, acc1 = 0ull, acc2 = 0ull, acc3 = 0ull;
        int hbase = cur * 64 + kh * 32;
#pragma unroll
        for (int ii = 0; ii < REGP / 2; ii++) {
            ulonglong2 hv = hsmV2[hbase + ii];
            acc0 = fma2(wreg[2 * ii],     hv.x, acc0);
            acc1 = fma2(wreg[2 * ii + 1], hv.y, acc1);
        }
#pragma unroll
        for (int ii = 0; ii < SMEMP / 2; ii++) {
            ulonglong2 hv = hsmV2[hbase + REGP / 2 + ii];
            ulonglong2 wv = wsmV2[(ii * 2 + kh) * 256 + u];
            acc2 = fma2(wv.x, hv.x, acc2);
            acc3 = fma2(wv.y, hv.y, acc3);
        }
        float s, x0, x1;
        unpack2(acc0, x0, x1); s  = x0 + x1;
        unpack2(acc1, x0, x1); s += x0 + x1;
        unpack2(acc2, x0, x1); s += x0 + x1;
        unpack2(acc3, x0, x1); s += x0 + x1;
        s += __shfl_xor_sync(0xffffffffu, s, 16);   // combine the two K-halves

        if (kh == 0) {
            float pre = s + Grow[(size_t)t * 512];
            if (isF) fbuf[colLocal] = 1.0f / (1.0f + __expf(-pre));
            else     cbuf[colLocal] = tanhf(pre);
        }
        __syncthreads();

        if (tid < 128) {
            int hidx = rank * 128 + tid;
            float f = fbuf[tid];
            float c = cbuf[tid];
            float hold = hsm[cur * 256 + hidx];
            float hn = c + f * (hold - c);            // f*h + (1-f)*c
            int nxt = cur ^ 1;
            hsm[nxt * 256 + hidx] = hn;
            // DSMEM store of our h slice into peer CTA's next buffer
            unsigned int la = (unsigned int)__cvta_generic_to_shared(&hsm[nxt * 256 + hidx]);
            unsigned int pa;
            int peer = rank ^ 1;
            asm("mapa.shared::cluster.u32 %0, %1, %2;" : "=r"(pa) : "r"(la), "r"(peer));
            asm volatile("st.shared::cluster.f32 [%0], %1;" :: "r"(pa), "f"(hn));
            Yrow[(size_t)t * HH + hidx] = hn;
        }
        // release our stores / acquire peer's before next step reads h
        asm volatile("barrier.cluster.arrive.aligned;" ::: "memory");
        asm volatile("barrier.cluster.wait.aligned;"   ::: "memory");
    }

    if (tid < 128) {
        int hidx = rank * 128 + tid;
        hidOut[(size_t)b * HH + hidx] = hsm[0 * 256 + hidx];   // final h is in buffer 0 (T even)
    }
}

// ---------------- host launch ----------------
static void launch_rec(const float* G, const float* Wf, const float* Wc, int xdim,
                       float* Y, float* hid)
{
    cudaLaunchConfig_t cfg = {};
    cfg.gridDim  = dim3(2 * BB, 1, 1);
    cfg.blockDim = dim3(REC_THREADS, 1, 1);
    cfg.dynamicSmemBytes = WSM_BYTES;
    cfg.stream = 0;
    cudaLaunchAttribute attr[1];
    attr[0].id = cudaLaunchAttributeClusterDimension;
    attr[0].val.clusterDim.x = 2;
    attr[0].val.clusterDim.y = 1;
    attr[0].val.clusterDim.z = 1;
    cfg.attrs = attr;
    cfg.numAttrs = 1;
    cudaLaunchKernelEx(&cfg, rec_kernel, G, Wf, Wc, xdim, Y, hid);
}

extern "C" void kernel_launch(void* const* d_in, const int* in_sizes, int n_in,
                              void* d_out, int out_size)
{
    (void)in_sizes; (void)n_in; (void)out_size;
    const float* x   = (const float*)d_in[0];
    const float* Wf1 = (const float*)d_in[1];
    const float* bf1 = (const float*)d_in[2];
    const float* Wc1 = (const float*)d_in[3];
    const float* bc1 = (const float*)d_in[4];
    const float* Wf2 = (const float*)d_in[5];
    const float* bf2 = (const float*)d_in[6];
    const float* Wc2 = (const float*)d_in[7];
    const float* bc2 = (const float*)d_in[8];

    float* out = (float*)d_out;
    float* y2  = out;                       // [B, T, H]
    float* hid = out + (size_t)YSZ;         // [2, B, H]

    float* G;  cudaGetSymbolAddress((void**)&G,  g_G);
    float* y1; cudaGetSymbolAddress((void**)&y1, g_y1);

    cudaFuncSetAttribute(rec_kernel, cudaFuncAttributeMaxDynamicSharedMemorySize, WSM_BYTES);

    dim3 ggrid(4, (BB * TT) / GM_BM);
    dim3 gblk(256);

    // Layer 1
    gemm_gates<<<ggrid, gblk>>>(x, II, II, Wf1, Wc1, bf1, bc1, G);
    launch_rec(G, Wf1, Wc1, II, y1, hid);                 // hidden layer-0 slot
    // Layer 2
    gemm_gates<<<ggrid, gblk>>>(y1, HH, HH, Wf2, Wc2, bf2, bc2, G);
    launch_rec(G, Wf2, Wc2, HH, y2, hid + (size_t)BB * HH);
}

// round 6
// speedup vs baseline: 1.2491x; 1.2491x over previous
#include <cuda_runtime.h>
#include <cuda_bf16.h>
#include <math.h>

// Problem dims
#define BB 64
#define TT 1024
#define II 128
#define HH 256
#define YSZ (BB*TT*HH)   // 16777216

// ---------------- scratch (device globals; no allocs allowed) ----------------
__device__ float g_G[BB * TT * 512];    // gate pre-activations (x-part + bias)
__device__ float g_y1[BB * TT * HH];    // layer-1 outputs

// ---------------- f32x2 helpers ----------------
__device__ __forceinline__ unsigned long long pack2(float lo, float hi) {
    unsigned long long r;
    asm("mov.b64 %0, {%1, %2};" : "=l"(r) : "f"(lo), "f"(hi));
    return r;
}
__device__ __forceinline__ void unpack2(unsigned long long v, float& lo, float& hi) {
    asm("mov.b64 {%0, %1}, %2;" : "=f"(lo), "=f"(hi) : "l"(v));
}
__device__ __forceinline__ unsigned long long fma2(unsigned long long a, unsigned long long b,
                                                   unsigned long long c) {
    unsigned long long d;
    asm("fma.rn.f32x2 %0, %1, %2, %3;" : "=l"(d) : "l"(a), "l"(b), "l"(c));
    return d;
}

// ---------------- GEMM: G[m, 0:512] = A[m,:K] @ {Wf|Wc}[:K,:256] + bias -------------
// Grid: (4 n-tiles of 128, M/128). nt 0,1 -> f gate cols ; nt 2,3 -> c gate cols
#define GM_BM 128
#define GM_BK 16

__global__ void __launch_bounds__(256) gemm_gates(
    const float* __restrict__ A, int lda, int K,
    const float* __restrict__ Wf, const float* __restrict__ Wc,
    const float* __restrict__ bf, const float* __restrict__ bc,
    float* __restrict__ G)
{
    __shared__ __align__(16) float As[GM_BK][GM_BM];
    __shared__ __align__(16) float Bs[GM_BK][GM_BM];

    int nt = blockIdx.x;
    int m0 = blockIdx.y * GM_BM;
    const float* W  = (nt < 2) ? Wf : Wc;
    const float* bs = (nt < 2) ? bf : bc;
    int nbase = (nt & 1) * 128;

    int tid = threadIdx.x;
    int tx = tid & 15;        // n dir, 8 cols each
    int ty = tid >> 4;        // m dir, 8 rows each

    int arow = tid >> 1;            // 0..127
    int acol = (tid & 1) * 8;       // 0 or 8
    int brow = tid >> 4;            // 0..15
    int bcol = (tid & 15) * 8;      // 0..120

    unsigned long long cc[8][4];
#pragma unroll
    for (int i = 0; i < 8; i++)
#pragma unroll
        for (int j = 0; j < 4; j++) cc[i][j] = 0ull;

    const float* Aptr = &A[(size_t)(m0 + arow) * lda + acol];
    const float* Bptr = &W[(size_t)brow * 256 + nbase + bcol];

    // preload tile 0
    float4 a0 = *reinterpret_cast<const float4*>(Aptr);
    float4 a1 = *reinterpret_cast<const float4*>(Aptr + 4);
    float4 b0 = *reinterpret_cast<const float4*>(Bptr);
    float4 b1 = *reinterpret_cast<const float4*>(Bptr + 4);

    for (int k0 = 0; k0 < K; k0 += GM_BK) {
        // commit current regs to smem
        As[acol + 0][arow] = a0.x; As[acol + 1][arow] = a0.y;
        As[acol + 2][arow] = a0.z; As[acol + 3][arow] = a0.w;
        As[acol + 4][arow] = a1.x; As[acol + 5][arow] = a1.y;
        As[acol + 6][arow] = a1.z; As[acol + 7][arow] = a1.w;
        *reinterpret_cast<float4*>(&Bs[brow][bcol])     = b0;
        *reinterpret_cast<float4*>(&Bs[brow][bcol + 4]) = b1;
        __syncthreads();

        if (k0 + GM_BK < K) {     // prefetch next tile
            const float* An = Aptr + (k0 + GM_BK);
            const float* Bn = Bptr + (size_t)(k0 + GM_BK) * 256;
            a0 = *reinterpret_cast<const float4*>(An);
            a1 = *reinterpret_cast<const float4*>(An + 4);
            b0 = *reinterpret_cast<const float4*>(Bn);
            b1 = *reinterpret_cast<const float4*>(Bn + 4);
        }
#pragma unroll
        for (int kk = 0; kk < GM_BK; kk++) {
            float a[8];
            *reinterpret_cast<float4*>(a)     = *reinterpret_cast<const float4*>(&As[kk][ty * 8]);
            *reinterpret_cast<float4*>(a + 4) = *reinterpret_cast<const float4*>(&As[kk][ty * 8 + 4]);
            const ulonglong2* bu2 = reinterpret_cast<const ulonglong2*>(&Bs[kk][tx * 8]);
            ulonglong2 b01 = bu2[0];
            ulonglong2 b23 = bu2[1];
            unsigned long long bp[4] = {b01.x, b01.y, b23.x, b23.y};
#pragma unroll
            for (int i = 0; i < 8; i++) {
                unsigned long long ap = pack2(a[i], a[i]);
#pragma unroll
                for (int j = 0; j < 4; j++) cc[i][j] = fma2(ap, bp[j], cc[i][j]);
            }
        }
        __syncthreads();
    }
#pragma unroll
    for (int i = 0; i < 8; i++) {
        int m = m0 + ty * 8 + i;
        float* gr = &G[(size_t)m * 512 + nt * 128 + tx * 8];
#pragma unroll
        for (int j = 0; j < 4; j++) {
            float lo, hi;
            unpack2(cc[i][j], lo, hi);
            int cl = nbase + tx * 8 + 2 * j;
            float2 st;
            st.x = lo + bs[cl];
            st.y = hi + bs[cl + 1];
            *reinterpret_cast<float2*>(&gr[2 * j]) = st;
        }
    }
}

// ---------------- Recurrent sweep ----------------
// 64 batches, one 2-CTA cluster per batch. CTA rank r owns h cols [128r,128r+128).
// Task map: warp w (0..15) owns local cols 8w..8w+7.
//   lane&7 -> col within warp; (lane>>3)&1 -> gate (0=f,1=c); lane>>4 -> K-half.
// Each thread: half-dot (K=128) for one (col,gate): 64 f32x2 pairs = 28 in regs + 36 in smem.
// Gate combine via shfl_xor(16) then shfl_xor(8). h_old lives in the writer's register.
// Per-step sync: ONE cluster barrier (release/acquire over smem + DSMEM).
#define REC_THREADS 512
#define REGP 28
#define SMEMP 36
#define WSM_V2 ((SMEMP/2) * 512)               // ulonglong2 elements (18*512)
#define WSM_BYTES (WSM_V2 * 16)                // 147456 bytes

__global__ void __launch_bounds__(REC_THREADS, 1) rec_kernel(
    const float* __restrict__ G, const float* __restrict__ Wf, const float* __restrict__ Wc,
    int xdim, float* __restrict__ Y, float* __restrict__ hidOut)
{
    extern __shared__ __align__(16) unsigned char smem_raw[];
    ulonglong2* wsmV2 = reinterpret_cast<ulonglong2*>(smem_raw);

    __shared__ __align__(16) float hsm[2 * 256];      // double-buffered full h

    int tid  = threadIdx.x;
    int b    = blockIdx.x >> 1;
    int rank = blockIdx.x & 1;
    int lane = tid & 31;
    int w    = tid >> 5;
    int isC  = (lane >> 3) & 1;
    int kh   = lane >> 4;
    int cl   = (w << 3) | (lane & 7);       // local col 0..127
    int gcol = rank * 128 + cl;             // global h col
    bool writer = (lane < 8);
    const float* Wsrc = (isC ? Wc : Wf) + (size_t)xdim * 256;  // h-part rows
    int kb = kh * 128;

    // --- load weights: 28 pairs in regs, 36 pairs (18 ulonglong2) in smem ---
    unsigned long long wreg[REGP];
#pragma unroll
    for (int i = 0; i < REGP; i++) {
        int k = kb + 2 * i;
        wreg[i] = pack2(Wsrc[(size_t)k * 256 + gcol], Wsrc[(size_t)(k + 1) * 256 + gcol]);
    }
#pragma unroll
    for (int j2 = 0; j2 < SMEMP / 2; j2++) {
        int k = kb + 2 * (REGP + 2 * j2);
        ulonglong2 wv;
        wv.x = pack2(Wsrc[(size_t)k * 256 + gcol],       Wsrc[(size_t)(k + 1) * 256 + gcol]);
        wv.y = pack2(Wsrc[(size_t)(k + 2) * 256 + gcol], Wsrc[(size_t)(k + 3) * 256 + gcol]);
        wsmV2[j2 * 512 + tid] = wv;
    }
    if (tid < 512) hsm[tid] = 0.0f;   // zero both h buffers
    __syncthreads();
    // cluster barrier: peer's smem init complete before any DSMEM traffic
    asm volatile("barrier.cluster.arrive.aligned;" ::: "memory");
    asm volatile("barrier.cluster.wait.aligned;"   ::: "memory");

    unsigned int hsmL = (unsigned int)__cvta_generic_to_shared(hsm);
    int peer = rank ^ 1;
    unsigned int hsmP;
    asm("mapa.shared::cluster.u32 %0, %1, %2;" : "=r"(hsmP) : "r"(hsmL), "r"(peer));

    const ulonglong2* hsmV2 = reinterpret_cast<const ulonglong2*>(hsm);
    int og = isC ? (256 + gcol) : gcol;
    const float* Gptr = G + (size_t)b * TT * 512 + og;
    float* Yrow = Y + (size_t)b * TT * HH;

    float h_reg = 0.0f;                 // h_old for this writer's column
    float gv = Gptr[0];                 // prefetched gate pre-activation (x-part)

    for (int t = 0; t < TT; t++) {
        int cur = t & 1;
        float gnext = (t + 1 < TT) ? Gptr[(size_t)(t + 1) * 512] : 0.0f;  // prefetch

        unsigned long long acc0 = 0ull, acc1 = 0ull, acc2 = 0ull, acc3 = 0ull;
        int hbase = cur * 64 + kh * 32;
#pragma unroll
        for (int i = 0; i < REGP / 2; i++) {
            ulonglong2 hv = hsmV2[hbase + i];
            acc0 = fma2(wreg[2 * i],     hv.x, acc0);
            acc1 = fma2(wreg[2 * i + 1], hv.y, acc1);
        }
#pragma unroll
        for (int j2 = 0; j2 < SMEMP / 2; j2++) {
            ulonglong2 hv = hsmV2[hbase + REGP / 2 + j2];
            ulonglong2 wv = wsmV2[j2 * 512 + tid];
            acc2 = fma2(wv.x, hv.x, acc2);
            acc3 = fma2(wv.y, hv.y, acc3);
        }
        float s, x0, x1;
        unpack2(acc0, x0, x1); s  = x0 + x1;
        unpack2(acc1, x0, x1); s += x0 + x1;
        unpack2(acc2, x0, x1); s += x0 + x1;
        unpack2(acc3, x0, x1); s += x0 + x1;
        // combine the two K-halves: lanes l and l^16 hold the two halves of same (col,gate)
        s += __shfl_xor_sync(0xffffffffu, s, 16);

        float pre = s + gv;
        gv = gnext;
        // activation: f lanes -> sigmoid, c lanes -> tanh (both via one MUFU exp)
        float act;
        if (isC) {
            float e = __expf(2.0f * pre);
            act = __fdividef(e - 1.0f, e + 1.0f);
        } else {
            act = __fdividef(1.0f, 1.0f + __expf(-pre));
        }
        // bring c into the f lanes (l<8): partner is l^8
        float other = __shfl_xor_sync(0xffffffffu, act, 8);

        if (writer) {
            float f = act, c = other;
            float hn = c + f * (h_reg - c);       // f*h + (1-f)*c
            h_reg = hn;
            int nxt = cur ^ 1;
            unsigned int off = (unsigned int)(nxt * 256 + gcol) * 4u;
            hsm[nxt * 256 + gcol] = hn;           // local
            asm volatile("st.shared::cluster.f32 [%0], %1;" :: "r"(hsmP + off), "f"(hn));
            Yrow[(size_t)t * HH + gcol] = hn;     // stream output
        }
        // single rendezvous per step: release our h stores, acquire peer's
        asm volatile("barrier.cluster.arrive.aligned;" ::: "memory");
        asm volatile("barrier.cluster.wait.aligned;"   ::: "memory");
    }

    if (writer) hidOut[(size_t)b * HH + gcol] = h_reg;
}

// ---------------- host launch ----------------
static void launch_rec(const float* G, const float* Wf, const float* Wc, int xdim,
                       float* Y, float* hid)
{
    cudaLaunchConfig_t cfg = {};
    cfg.gridDim  = dim3(2 * BB, 1, 1);
    cfg.blockDim = dim3(REC_THREADS, 1, 1);
    cfg.dynamicSmemBytes = WSM_BYTES;
    cfg.stream = 0;
    cudaLaunchAttribute attr[1];
    attr[0].id = cudaLaunchAttributeClusterDimension;
    attr[0].val.clusterDim.x = 2;
    attr[0].val.clusterDim.y = 1;
    attr[0].val.clusterDim.z = 1;
    cfg.attrs = attr;
    cfg.numAttrs = 1;
    cudaLaunchKernelEx(&cfg, rec_kernel, G, Wf, Wc, xdim, Y, hid);
}

extern "C" void kernel_launch(void* const* d_in, const int* in_sizes, int n_in,
                              void* d_out, int out_size)
{
    (void)in_sizes; (void)n_in; (void)out_size;
    const float* x   = (const float*)d_in[0];
    const float* Wf1 = (const float*)d_in[1];
    const float* bf1 = (const float*)d_in[2];
    const float* Wc1 = (const float*)d_in[3];
    const float* bc1 = (const float*)d_in[4];
    const float* Wf2 = (const float*)d_in[5];
    const float* bf2 = (const float*)d_in[6];
    const float* Wc2 = (const float*)d_in[7];
    const float* bc2 = (const float*)d_in[8];

    float* out = (float*)d_out;
    float* y2  = out;                       // [B, T, H]
    float* hid = out + (size_t)YSZ;         // [2, B, H]

    float* G;  cudaGetSymbolAddress((void**)&G,  g_G);
    float* y1; cudaGetSymbolAddress((void**)&y1, g_y1);

    cudaFuncSetAttribute(rec_kernel, cudaFuncAttributeMaxDynamicSharedMemorySize, WSM_BYTES);

    dim3 ggrid(4, (BB * TT) / GM_BM);
    dim3 gblk(256);

    // Layer 1
    gemm_gates<<<ggrid, gblk>>>(x, II, II, Wf1, Wc1, bf1, bc1, G);
    launch_rec(G, Wf1, Wc1, II, y1, hid);
    // Layer 2
    gemm_gates<<<ggrid, gblk>>>(y1, HH, HH, Wf2, Wc2, bf2, bc2, G);
    launch_rec(G, Wf2, Wc2, HH, y2, hid + (size_t)BB * HH);
}

// round 7
// speedup vs baseline: 1.4127x; 1.1310x over previous
#include <cuda_runtime.h>
#include <cuda_bf16.h>
#include <math.h>

// Problem dims
#define BB 64
#define TT 1024
#define II 128
#define HH 256
#define YSZ (BB*TT*HH)   // 16777216

// ---------------- scratch (device globals; no allocs allowed) ----------------
__device__ float g_G[BB * TT * 512];    // gate pre-activations (x-part + bias)
__device__ float g_y1[BB * TT * HH];    // layer-1 outputs

// ---------------- f32x2 helpers ----------------
__device__ __forceinline__ unsigned long long pack2(float lo, float hi) {
    unsigned long long r;
    asm("mov.b64 %0, {%1, %2};" : "=l"(r) : "f"(lo), "f"(hi));
    return r;
}
__device__ __forceinline__ void unpack2(unsigned long long v, float& lo, float& hi) {
    asm("mov.b64 {%0, %1}, %2;" : "=f"(lo), "=f"(hi) : "l"(v));
}
__device__ __forceinline__ unsigned long long fma2(unsigned long long a, unsigned long long b,
                                                   unsigned long long c) {
    unsigned long long d;
    asm("fma.rn.f32x2 %0, %1, %2, %3;" : "=l"(d) : "l"(a), "l"(b), "l"(c));
    return d;
}
// bf16x2 (lo=w[k], hi=w[k+1]) -> f32x2 via shift/mask (2 ALU ops)
__device__ __forceinline__ unsigned long long bf2_to_f32x2(unsigned int v) {
    unsigned int lo = v << 16;
    unsigned int hi = v & 0xFFFF0000u;
    return pack2(__uint_as_float(lo), __uint_as_float(hi));
}

// ---------------- GEMM: G[m, 0:512] = A[m,:K] @ {Wf|Wc}[:K,:256] + bias -------------
#define GM_BM 128
#define GM_BK 16

__global__ void __launch_bounds__(256) gemm_gates(
    const float* __restrict__ A, int lda, int K,
    const float* __restrict__ Wf, const float* __restrict__ Wc,
    const float* __restrict__ bf, const float* __restrict__ bc,
    float* __restrict__ G)
{
    __shared__ __align__(16) float As[GM_BK][GM_BM];
    __shared__ __align__(16) float Bs[GM_BK][GM_BM];

    int nt = blockIdx.x;
    int m0 = blockIdx.y * GM_BM;
    const float* W  = (nt < 2) ? Wf : Wc;
    const float* bs = (nt < 2) ? bf : bc;
    int nbase = (nt & 1) * 128;

    int tid = threadIdx.x;
    int tx = tid & 15;        // n dir, 8 cols each
    int ty = tid >> 4;        // m dir, 8 rows each

    int arow = tid >> 1;            // 0..127
    int acol = (tid & 1) * 8;       // 0 or 8
    int brow = tid >> 4;            // 0..15
    int bcol = (tid & 15) * 8;      // 0..120

    unsigned long long cc[8][4];
#pragma unroll
    for (int i = 0; i < 8; i++)
#pragma unroll
        for (int j = 0; j < 4; j++) cc[i][j] = 0ull;

    const float* Aptr = &A[(size_t)(m0 + arow) * lda + acol];
    const float* Bptr = &W[(size_t)brow * 256 + nbase + bcol];

    float4 a0 = *reinterpret_cast<const float4*>(Aptr);
    float4 a1 = *reinterpret_cast<const float4*>(Aptr + 4);
    float4 b0 = *reinterpret_cast<const float4*>(Bptr);
    float4 b1 = *reinterpret_cast<const float4*>(Bptr + 4);

    for (int k0 = 0; k0 < K; k0 += GM_BK) {
        As[acol + 0][arow] = a0.x; As[acol + 1][arow] = a0.y;
        As[acol + 2][arow] = a0.z; As[acol + 3][arow] = a0.w;
        As[acol + 4][arow] = a1.x; As[acol + 5][arow] = a1.y;
        As[acol + 6][arow] = a1.z; As[acol + 7][arow] = a1.w;
        *reinterpret_cast<float4*>(&Bs[brow][bcol])     = b0;
        *reinterpret_cast<float4*>(&Bs[brow][bcol + 4]) = b1;
        __syncthreads();

        if (k0 + GM_BK < K) {
            const float* An = Aptr + (k0 + GM_BK);
            const float* Bn = Bptr + (size_t)(k0 + GM_BK) * 256;
            a0 = *reinterpret_cast<const float4*>(An);
            a1 = *reinterpret_cast<const float4*>(An + 4);
            b0 = *reinterpret_cast<const float4*>(Bn);
            b1 = *reinterpret_cast<const float4*>(Bn + 4);
        }
#pragma unroll
        for (int kk = 0; kk < GM_BK; kk++) {
            float a[8];
            *reinterpret_cast<float4*>(a)     = *reinterpret_cast<const float4*>(&As[kk][ty * 8]);
            *reinterpret_cast<float4*>(a + 4) = *reinterpret_cast<const float4*>(&As[kk][ty * 8 + 4]);
            const ulonglong2* bu2 = reinterpret_cast<const ulonglong2*>(&Bs[kk][tx * 8]);
            ulonglong2 b01 = bu2[0];
            ulonglong2 b23 = bu2[1];
            unsigned long long bp[4] = {b01.x, b01.y, b23.x, b23.y};
#pragma unroll
            for (int i = 0; i < 8; i++) {
                unsigned long long ap = pack2(a[i], a[i]);
#pragma unroll
                for (int j = 0; j < 4; j++) cc[i][j] = fma2(ap, bp[j], cc[i][j]);
            }
        }
        __syncthreads();
    }
#pragma unroll
    for (int i = 0; i < 8; i++) {
        int m = m0 + ty * 8 + i;
        float* gr = &G[(size_t)m * 512 + nt * 128 + tx * 8];
#pragma unroll
        for (int j = 0; j < 4; j++) {
            float lo, hi;
            unpack2(cc[i][j], lo, hi);
            int cl = nbase + tx * 8 + 2 * j;
            float2 st;
            st.x = lo + bs[cl];
            st.y = hi + bs[cl + 1];
            *reinterpret_cast<float2*>(&gr[2 * j]) = st;
        }
    }
}

// ---------------- Recurrent sweep ----------------
// 64 batches, one 2-CTA cluster per batch. CTA rank r owns h cols [128r,128r+128).
// warp w owns local cols 8w..8w+7; lane&7 col, (lane>>3)&1 gate, lane>>4 K-half.
// Per-thread half-dot (K=128): 28 f32x2 pairs in regs + 36 bf16x2 pairs in smem
// (9 x LDS.128 per step, decompressed with shift/mask on the ALU pipe).
// Per-step sync: two-mbarrier ping-pong, warp-aggregated arrives (32) on local+peer.
#define REC_THREADS 512
#define REGP 28
#define SMEMP 36                               // bf16 pairs in smem
#define WSM_U4 ((SMEMP/4) * 512)               // uint4 elements: 9*512
#define WSM_BYTES (WSM_U4 * 16)                // 73728 bytes

__global__ void __launch_bounds__(REC_THREADS, 1) rec_kernel(
    const float* __restrict__ G, const float* __restrict__ Wf, const float* __restrict__ Wc,
    int xdim, float* __restrict__ Y, float* __restrict__ hidOut)
{
    extern __shared__ __align__(16) unsigned char smem_raw[];
    uint4* wsm4 = reinterpret_cast<uint4*>(smem_raw);

    __shared__ __align__(16) float hsm[2 * 256];          // double-buffered full h
    __shared__ __align__(8)  unsigned long long mbar[2];  // ping-pong barriers

    int tid  = threadIdx.x;
    int b    = blockIdx.x >> 1;
    int rank = blockIdx.x & 1;
    int lane = tid & 31;
    int w    = tid >> 5;
    int isC  = (lane >> 3) & 1;
    int kh   = lane >> 4;
    int cl   = (w << 3) | (lane & 7);       // local col 0..127
    int gcol = rank * 128 + cl;             // global h col
    bool writer = (lane < 8);
    const float* Wsrc = (isC ? Wc : Wf) + (size_t)xdim * 256;  // h-part rows
    int kb = kh * 128;

    // --- weights: 28 f32x2 pairs in regs ---
    unsigned long long wreg[REGP];
#pragma unroll
    for (int i = 0; i < REGP; i++) {
        int k = kb + 2 * i;
        wreg[i] = pack2(Wsrc[(size_t)k * 256 + gcol], Wsrc[(size_t)(k + 1) * 256 + gcol]);
    }
    // --- weights: 36 bf16x2 pairs in smem (9 uint4 per thread) ---
#pragma unroll
    for (int j = 0; j < SMEMP / 4; j++) {
        unsigned int q[4];
#pragma unroll
        for (int p = 0; p < 4; p++) {
            int k = kb + 2 * (REGP + 4 * j + p);
            __nv_bfloat162 bb = __floats2bfloat162_rn(Wsrc[(size_t)k * 256 + gcol],
                                                      Wsrc[(size_t)(k + 1) * 256 + gcol]);
            q[p] = *reinterpret_cast<unsigned int*>(&bb);
        }
        uint4 v; v.x = q[0]; v.y = q[1]; v.z = q[2]; v.w = q[3];
        wsm4[j * 512 + tid] = v;
    }
    if (tid < 512) hsm[tid] = 0.0f;   // zero both h buffers
    if (tid == 0) {
        unsigned int ba = (unsigned int)__cvta_generic_to_shared(&mbar[0]);
        asm volatile("mbarrier.init.shared.b64 [%0], %1;" :: "r"(ba),     "r"(1024) : "memory");
        asm volatile("mbarrier.init.shared.b64 [%0], %1;" :: "r"(ba + 8), "r"(1024) : "memory");
    }
    __syncthreads();
    // one cluster barrier: peer smem init + mbarrier init visible before any traffic
    asm volatile("barrier.cluster.arrive.aligned;" ::: "memory");
    asm volatile("barrier.cluster.wait.aligned;"   ::: "memory");

    unsigned int hsmL = (unsigned int)__cvta_generic_to_shared(hsm);
    unsigned int barL = (unsigned int)__cvta_generic_to_shared(&mbar[0]);
    int peer = rank ^ 1;
    unsigned int hsmP, barP;
    asm("mapa.shared::cluster.u32 %0, %1, %2;" : "=r"(hsmP) : "r"(hsmL), "r"(peer));
    asm("mapa.shared::cluster.u32 %0, %1, %2;" : "=r"(barP) : "r"(barL), "r"(peer));

    const ulonglong2* hsmV2 = reinterpret_cast<const ulonglong2*>(hsm);
    int og = isC ? (256 + gcol) : gcol;
    const float* Gptr = G + (size_t)b * TT * 512 + og;
    float* Yrow = Y + (size_t)b * TT * HH;

    float h_reg = 0.0f;                 // h_old for this writer's column
    float gv = Gptr[0];                 // prefetched gate pre-activation (x-part)

    for (int t = 0; t < TT; t++) {
        int cur = t & 1;
        float gnext = (t + 1 < TT) ? Gptr[(size_t)(t + 1) * 512] : 0.0f;  // prefetch

        unsigned long long acc0 = 0ull, acc1 = 0ull, acc2 = 0ull, acc3 = 0ull;
        int hbase = cur * 64 + kh * 32;
#pragma unroll
        for (int i = 0; i < REGP / 2; i++) {            // 14 v2 of h, reg weights
            ulonglong2 hv = hsmV2[hbase + i];
            acc0 = fma2(wreg[2 * i],     hv.x, acc0);
            acc1 = fma2(wreg[2 * i + 1], hv.y, acc1);
        }
#pragma unroll
        for (int j = 0; j < SMEMP / 4; j++) {           // 9 uint4 of bf16 weights
            uint4 wv = wsm4[j * 512 + tid];
            ulonglong2 h0 = hsmV2[hbase + REGP / 2 + 2 * j];
            ulonglong2 h1 = hsmV2[hbase + REGP / 2 + 2 * j + 1];
            acc2 = fma2(bf2_to_f32x2(wv.x), h0.x, acc2);
            acc3 = fma2(bf2_to_f32x2(wv.y), h0.y, acc3);
            acc2 = fma2(bf2_to_f32x2(wv.z), h1.x, acc2);
            acc3 = fma2(bf2_to_f32x2(wv.w), h1.y, acc3);
        }
        float s, x0, x1;
        unpack2(acc0, x0, x1); s  = x0 + x1;
        unpack2(acc1, x0, x1); s += x0 + x1;
        unpack2(acc2, x0, x1); s += x0 + x1;
        unpack2(acc3, x0, x1); s += x0 + x1;
        // combine the two K-halves (lanes l, l^16)
        s += __shfl_xor_sync(0xffffffffu, s, 16);

        float pre = s + gv;
        gv = gnext;
        float act;
        if (isC) {
            float e = __expf(2.0f * pre);
            act = __fdividef(e - 1.0f, e + 1.0f);       // tanh
        } else {
            act = __fdividef(1.0f, 1.0f + __expf(-pre)); // sigmoid
        }
        float other = __shfl_xor_sync(0xffffffffu, act, 8);  // bring c to f lanes

        if (writer) {
            float f = act, c = other;
            float hn = c + f * (h_reg - c);             // f*h + (1-f)*c
            h_reg = hn;
            int nxt = cur ^ 1;
            unsigned int off = (unsigned int)(nxt * 256 + gcol) * 4u;
            hsm[nxt * 256 + gcol] = hn;                 // local
            asm volatile("st.shared::cluster.f32 [%0], %1;" :: "r"(hsmP + off), "f"(hn));
            Yrow[(size_t)t * HH + gcol] = hn;           // stream output
        }
        // ---- ping-pong mbarrier sync (one rendezvous per step) ----
        __syncwarp();
        unsigned int sel = (unsigned int)(cur) * 8u;
        if (lane == 0) {
            asm volatile("mbarrier.arrive.release.cluster.shared::cluster.b64 _, [%0], %1;"
                         :: "r"(barP + sel), "r"(32) : "memory");
            asm volatile("mbarrier.arrive.release.cta.shared::cta.b64 _, [%0], %1;"
                         :: "r"(barL + sel), "r"(32) : "memory");
        }
        {
            unsigned int parity = (unsigned int)((t >> 1) & 1);
            unsigned int done;
            asm volatile(
                "{\n\t"
                ".reg .pred p;\n\t"
                "mbarrier.try_wait.parity.acquire.cluster.shared::cta.b64 p, [%1], %2;\n\t"
                "selp.b32 %0, 1, 0, p;\n\t"
                "}"
                : "=r"(done) : "r"(barL + sel), "r"(parity) : "memory");
            if (!done) {
                asm volatile(
                    "{\n\t"
                    ".reg .pred P1;\n\t"
                    "WAIT_LOOP_%=:\n\t"
                    "mbarrier.try_wait.parity.acquire.cluster.shared::cta.b64 P1, [%0], %1, 0x989680;\n\t"
                    "@P1 bra.uni WAIT_DONE_%=;\n\t"
                    "bra.uni WAIT_LOOP_%=;\n\t"
                    "WAIT_DONE_%=:\n\t"
                    "}"
                    :: "r"(barL + sel), "r"(parity) : "memory");
            }
        }
    }

    if (writer) hidOut[(size_t)b * HH + gcol] = h_reg;
}

// ---------------- host launch ----------------
static void launch_rec(const float* G, const float* Wf, const float* Wc, int xdim,
                       float* Y, float* hid)
{
    cudaLaunchConfig_t cfg = {};
    cfg.gridDim  = dim3(2 * BB, 1, 1);
    cfg.blockDim = dim3(REC_THREADS, 1, 1);
    cfg.dynamicSmemBytes = WSM_BYTES;
    cfg.stream = 0;
    cudaLaunchAttribute attr[1];
    attr[0].id = cudaLaunchAttributeClusterDimension;
    attr[0].val.clusterDim.x = 2;
    attr[0].val.clusterDim.y = 1;
    attr[0].val.clusterDim.z = 1;
    cfg.attrs = attr;
    cfg.numAttrs = 1;
    cudaLaunchKernelEx(&cfg, rec_kernel, G, Wf, Wc, xdim, Y, hid);
}

extern "C" void kernel_launch(void* const* d_in, const int* in_sizes, int n_in,
                              void* d_out, int out_size)
{
    (void)in_sizes; (void)n_in; (void)out_size;
    const float* x   = (const float*)d_in[0];
    const float* Wf1 = (const float*)d_in[1];
    const float* bf1 = (const float*)d_in[2];
    const float* Wc1 = (const float*)d_in[3];
    const float* bc1 = (const float*)d_in[4];
    const float* Wf2 = (const float*)d_in[5];
    const float* bf2 = (const float*)d_in[6];
    const float* Wc2 = (const float*)d_in[7];
    const float* bc2 = (const float*)d_in[8];

    float* out = (float*)d_out;
    float* y2  = out;                       // [B, T, H]
    float* hid = out + (size_t)YSZ;         // [2, B, H]

    float* G;  cudaGetSymbolAddress((void**)&G,  g_G);
    float* y1; cudaGetSymbolAddress((void**)&y1, g_y1);

    cudaFuncSetAttribute(rec_kernel, cudaFuncAttributeMaxDynamicSharedMemorySize, WSM_BYTES);

    dim3 ggrid(4, (BB * TT) / GM_BM);
    dim3 gblk(256);

    // Layer 1
    gemm_gates<<<ggrid, gblk>>>(x, II, II, Wf1, Wc1, bf1, bc1, G);
    launch_rec(G, Wf1, Wc1, II, y1, hid);
    // Layer 2
    gemm_gates<<<ggrid, gblk>>>(y1, HH, HH, Wf2, Wc2, bf2, bc2, G);
    launch_rec(G, Wf2, Wc2, HH, y2, hid + (size_t)BB * HH);
}